// round 12
// baseline (speedup 1.0000x reference)
#include <cuda_runtime.h>
#include <cuda_fp16.h>
#include <cstdint>
#include <cstring>

#define D        128
#define NREL     16
#define NBASES   8
#define TILE     64                                // rows per tile
#define CHUNK    4                                 // tiles per CTA
#define MAXE     600000
#define NTILES   ((MAXE / TILE) + NREL + 2)        // 9393 edge-tile capacity
#define SORT_CAP (NTILES * TILE)                   // 601152

// ---- smem layout (fp16 tiles, row stride 136 elems = 272B) ----
#define LDA      136
#define ROWB     (LDA * 2)          // 272 bytes per row
#define XTILE_B  (TILE * ROWB)      // 17408 (64-row X tile)
#define WTILE_B  (D * ROWB)         // 34816 (128-row W tile)
#define X_OFF    0
#define W_OFF    XTILE_B
#define GEMM_SMEM (XTILE_B + WTILE_B)              // 52224 -> 4 CTAs/SM

// -------- device scratch --------
__device__ __align__(16) __half g_W[NREL * D * D];   // [r][o][i] fp16
__device__ __align__(16) __half g_Ws[D * D];         // w_self [o][i] fp16
__device__ int g_counts[NREL];
__device__ int g_cursor[NREL];
__device__ int g_sorted[SORT_CAP];
__device__ int g_i32 = 0;   // sticky dtype flag: deterministic for fixed inputs

__device__ __forceinline__ int ld_idx(const void* p, size_t i, int is32) {
    return is32 ? ((const int*)p)[i] : (int)((const long long*)p)[i];
}
__device__ __forceinline__ void red2(float* p, float a, float b) {
    asm volatile("red.global.add.v2.f32 [%0], {%1,%2};"
                 :: "l"(p), "f"(a), "f"(b) : "memory");
}
__device__ __forceinline__ uint32_t smem_u32(const void* p) {
    uint32_t a;
    asm("{ .reg .u64 t; cvta.to.shared.u64 t, %1; cvt.u32.u64 %0, t; }" : "=r"(a) : "l"(p));
    return a;
}
__device__ __forceinline__ void ldsm4(uint32_t* r, uint32_t addr) {
    asm volatile("ldmatrix.sync.aligned.m8n8.x4.shared.b16 {%0,%1,%2,%3}, [%4];"
                 : "=r"(r[0]), "=r"(r[1]), "=r"(r[2]), "=r"(r[3]) : "r"(addr));
}
__device__ __forceinline__ void mma16816(float* c, const uint32_t* a,
                                         uint32_t b0, uint32_t b1) {
    asm volatile(
        "mma.sync.aligned.m16n8k16.row.col.f32.f16.f16.f32 "
        "{%0,%1,%2,%3}, {%4,%5,%6,%7}, {%8,%9}, {%0,%1,%2,%3};"
        : "+f"(c[0]), "+f"(c[1]), "+f"(c[2]), "+f"(c[3])
        : "r"(a[0]), "r"(a[1]), "r"(a[2]), "r"(a[3]), "r"(b0), "r"(b1));
}

// ================= fused init =================
__global__ void init_k(const void* __restrict__ etype,
                       const float* __restrict__ bases,
                       const float* __restrict__ coeff,
                       const float* __restrict__ wself, int E) {
    int i = blockIdx.x * blockDim.x + threadIdx.x;
    if (i < NREL) { g_counts[i] = 0; g_cursor[i] = 0; }
    if (i < SORT_CAP) g_sorted[i] = -1;
    if (i < 32768 && i < E / 2) {
        if (((const int*)etype)[2 * i + 1] != 0 && g_i32 == 0) atomicExch(&g_i32, 1);
    }
    if (i < NREL * D * D) {
        int r = i >> 14, o = (i >> 7) & 127, ii = i & 127;
        float acc = 0.f;
#pragma unroll
        for (int b = 0; b < NBASES; b++)
            acc += __ldg(&coeff[r * NBASES + b]) * __ldg(&bases[b * D * D + ii * D + o]);
        g_W[i] = __float2half_rn(acc);
    }
    if (i < D * D) g_Ws[i] = __float2half_rn(wself[i]);   // already [o][i]
}

// ================= histogram (smem-aggregated) =================
__global__ void hist_k(const void* __restrict__ etype, int E) {
    __shared__ int h[NREL];
    int tid = threadIdx.x;
    if (tid < NREL) h[tid] = 0;
    __syncthreads();
    int i = blockIdx.x * blockDim.x + tid;
    int is32 = g_i32;
    if (i < E) {
        int t = ld_idx(etype, i, is32);
        if (t >= 0 && t < NREL) atomicAdd(&h[t], 1);
    }
    __syncthreads();
    if (tid < NREL && h[tid] > 0) atomicAdd(&g_counts[tid], h[tid]);
}

// ================= scatter (scan fused per block) =================
__global__ void scatter_k(const void* __restrict__ etype, int E) {
    __shared__ int cnt[NREL], base[NREL], soff[NREL];
    int tid = threadIdx.x;
    if (tid < NREL) cnt[tid] = 0;
    if (tid == 0) {
        int off = 0;
        for (int r = 0; r < NREL; r++) {
            soff[r] = off;
            off += ((g_counts[r] + TILE - 1) / TILE) * TILE;
        }
    }
    __syncthreads();
    int i = blockIdx.x * blockDim.x + tid;
    int is32 = g_i32;
    int t = -1, rank = 0;
    if (i < E) {
        t = ld_idx(etype, i, is32);
        if (t >= 0 && t < NREL) rank = atomicAdd(&cnt[t], 1);
        else t = -1;
    }
    __syncthreads();
    if (tid < NREL && cnt[tid] > 0) base[tid] = atomicAdd(&g_cursor[tid], cnt[tid]);
    __syncthreads();
    if (t >= 0) g_sorted[soff[t] + base[t] + rank] = i;
}

// ================= GEMM helpers =================
extern __shared__ char smem_raw[];

__device__ __forceinline__ void cvt_store(char* sm, int e, int lane, float4 v) {
    __half2 p0 = __floats2half2_rn(v.x, v.y);
    __half2 p1 = __floats2half2_rn(v.z, v.w);
    uint32_t u0, u1;
    memcpy(&u0, &p0, 4); memcpy(&u1, &p1, 4);
    uint32_t off = (uint32_t)e * ROWB + (uint32_t)lane * 8;
    *(uint2*)(sm + X_OFF + off) = make_uint2(u0, u1);
}

// load W tile from global [o][i] fp16 (2048 16B chunks), 128 threads
__device__ __forceinline__ void load_w(char* sm, const __half* W, int tid) {
#pragma unroll
    for (int it = 0; it < 16; it++) {
        int c = it * 128 + tid;
        int o = c >> 4, k16 = (c & 15) * 16;
        *(uint4*)(sm + W_OFF + o * ROWB + k16) = ((const uint4*)W)[c];
    }
}

// ================= unified multi-tile GEMM (fat warps: 32x64 per warp) =================
__global__ __launch_bounds__(128, 4)
void gemm_k(const float* __restrict__ x,
            const void* __restrict__ eidx,
            const void* __restrict__ etype,
            float* __restrict__ out, int E, int N, int nEdgeTiles, int nTotal) {
    __shared__ int srow[TILE];
    char* sm = smem_raw;
    const int tid = threadIdx.x;
    const int warp = tid >> 5, lane = tid & 31;
    const int is32 = g_i32;

    // 2m x 2n warp grid; warp tile 32(m) x 64(n)
    const int wm = warp & 1, wn = warp >> 1;
    const int gq = lane >> 2, t4 = lane & 3;
    const int ar = (lane & 7) + ((lane >> 3) & 1) * 8;   // A ldmatrix row map
    const int ac = (lane >> 4) * 8;
    const int bn = (lane >> 4) * 8 + (lane & 7);         // B ldmatrix row map
    const int bk = ((lane >> 3) & 1) * 8;
    const uint32_t xb = smem_u32(sm + X_OFF) + (uint32_t)((wm * 32 + ar) * ROWB + ac * 2);
    const uint32_t wb = smem_u32(sm + W_OFF) + (uint32_t)((wn * 64 + bn) * ROWB + bk * 2);

    int cur_rel = -2;
    const int tEnd = min((int)blockIdx.x * CHUNK + CHUNK, nTotal);

    for (int tIdx = (int)blockIdx.x * CHUNK; tIdx < tEnd; tIdx++) {
        const bool isEdge = tIdx < nEdgeTiles;
        int rel, loc;
        if (isEdge) {
            loc = tIdx * TILE;
            int id0 = g_sorted[loc];
            rel = (id0 >= 0) ? ld_idx(etype, id0, is32) : -1;
        } else {
            loc = (tIdx - nEdgeTiles) * TILE;
            rel = NREL;
        }

        if (rel >= 0) {
            if (rel != cur_rel) {
                load_w(sm, (rel < NREL) ? (g_W + (size_t)rel * D * D) : g_Ws, tid);
                cur_rel = rel;
            }
            // per-warp index load (lane<16) + shfl broadcast; 16 rows per warp
            int r = -1, c = 0;
            if (lane < 16) {
                int e = warp * 16 + lane;
                if (isEdge) {
                    int id = g_sorted[loc + e];
                    if (id >= 0) {
                        r = ld_idx(eidx, id, is32);
                        c = ld_idx(eidx, (size_t)E + id, is32);
                        if ((unsigned)r >= (unsigned)N) r = -1;
                        if ((unsigned)c >= (unsigned)N) c = 0;
                    }
                } else {
                    int n = loc + e;
                    r = (n < N) ? n : -1;
                    c = (n < N) ? n : 0;
                }
                srow[e] = r;
            }
#pragma unroll
            for (int j = 0; j < 16; j++) {
                int cj = __shfl_sync(0xffffffffu, c, j);
                float4 v = ((const float4*)(x + (size_t)cj * D))[lane];
                cvt_store(sm, warp * 16 + j, lane, v);
            }
        }
        __syncthreads();                       // X/W/srow visible

        if (rel >= 0) {
            float acc[2][8][4];
#pragma unroll
            for (int mt = 0; mt < 2; mt++)
#pragma unroll
                for (int nt = 0; nt < 8; nt++)
#pragma unroll
                    for (int q = 0; q < 4; q++) acc[mt][nt][q] = 0.f;

#pragma unroll
            for (int kk = 0; kk < 8; kk++) {
                const uint32_t koff = (uint32_t)(kk * 16 * 2);
                uint32_t a[2][4], b[4][4];
#pragma unroll
                for (int mt = 0; mt < 2; mt++)
                    ldsm4(a[mt], xb + (uint32_t)(mt * 16 * ROWB) + koff);
#pragma unroll
                for (int n2 = 0; n2 < 4; n2++)
                    ldsm4(b[n2], wb + (uint32_t)(n2 * 16 * ROWB) + koff);
#pragma unroll
                for (int mt = 0; mt < 2; mt++)
#pragma unroll
                    for (int nt = 0; nt < 8; nt++)
                        mma16816(acc[mt][nt], a[mt], b[nt >> 1][(nt & 1) * 2],
                                 b[nt >> 1][(nt & 1) * 2 + 1]);
            }

            // epilogue straight from accumulators
#pragma unroll
            for (int mt = 0; mt < 2; mt++) {
                const int m0 = wm * 32 + mt * 16 + gq;
                const int r0 = srow[m0], r1 = srow[m0 + 8];
#pragma unroll
                for (int nt = 0; nt < 8; nt++) {
                    const int col = wn * 64 + nt * 8 + 2 * t4;
                    if (r0 >= 0) red2(out + (size_t)r0 * D + col, acc[mt][nt][0], acc[mt][nt][1]);
                    if (r1 >= 0) red2(out + (size_t)r1 * D + col, acc[mt][nt][2], acc[mt][nt][3]);
                }
            }
        }
        __syncthreads();                       // protect X/W/srow for next tile
    }
}

// ================= host launcher =================
extern "C" void kernel_launch(void* const* d_in, const int* in_sizes, int n_in,
                              void* d_out, int out_size) {
    const float* x     = (const float*)d_in[0];
    const void*  eidx  = d_in[1];
    const void*  etype = d_in[2];
    const float* bases = (const float*)d_in[3];
    const float* coeff = (const float*)d_in[4];
    const float* wself = (const float*)d_in[5];
    float* out = (float*)d_out;

    const int N = in_sizes[0] / D;
    const int E = in_sizes[2];
    const int nSelfTiles = (N + TILE - 1) / TILE;
    const int nTotal = NTILES + nSelfTiles;
    const int nBlocks = (nTotal + CHUNK - 1) / CHUNK;

    cudaFuncSetAttribute(gemm_k, cudaFuncAttributeMaxDynamicSharedMemorySize, GEMM_SMEM);
    cudaFuncSetAttribute(gemm_k, cudaFuncAttributePreferredSharedMemoryCarveout, 100);

    cudaMemsetAsync(out, 0, (size_t)out_size * sizeof(float));
    init_k<<<(SORT_CAP + 255) / 256, 256>>>(etype, bases, coeff, wself, E);
    hist_k<<<(E + 255) / 256, 256>>>(etype, E);
    scatter_k<<<(E + 255) / 256, 256>>>(etype, E);
    gemm_k<<<nBlocks, 128, GEMM_SMEM>>>(x, eidx, etype, out, E, N, NTILES, nTotal);
}

// round 13
// speedup vs baseline: 1.0065x; 1.0065x over previous
#include <cuda_runtime.h>
#include <cuda_fp16.h>
#include <cstdint>
#include <cstring>

#define D        128
#define NREL     16
#define NBASES   8
#define TILE     64                                // rows per tile
#define CHUNK    4                                 // tiles per CTA
#define MAXE     600000
#define NMAX     100352
#define NTILES   ((MAXE / TILE) + NREL + 2)        // 9393 edge-tile capacity
#define SORT_CAP (NTILES * TILE)                   // 601152

// ---- smem layout (fp16 tiles, row stride 136 elems = 272B) ----
#define LDA      136
#define ROWB     (LDA * 2)          // 272 bytes per row
#define XTILE_B  (TILE * ROWB)      // 17408 per X buffer
#define WTILE_B  (D * ROWB)         // 34816 (128-row W tile)
#define W_OFF    (2 * XTILE_B)
#define GEMM_SMEM (2 * XTILE_B + WTILE_B)          // 69632 -> 3 CTAs/SM

// -------- device scratch --------
__device__ __align__(16) __half g_xh[(size_t)NMAX * D];  // pre-converted X (25.7MB)
__device__ __align__(16) __half g_W[NREL * D * D];   // [r][o][i] fp16
__device__ __align__(16) __half g_Ws[D * D];         // w_self [o][i] fp16
__device__ int g_counts[NREL];
__device__ int g_cursor[NREL];
__device__ int g_sorted[SORT_CAP];
__device__ int g_i32 = 0;   // sticky dtype flag: deterministic for fixed inputs

__device__ __forceinline__ int ld_idx(const void* p, size_t i, int is32) {
    return is32 ? ((const int*)p)[i] : (int)((const long long*)p)[i];
}
__device__ __forceinline__ void red2(float* p, float a, float b) {
    asm volatile("red.global.add.v2.f32 [%0], {%1,%2};"
                 :: "l"(p), "f"(a), "f"(b) : "memory");
}
__device__ __forceinline__ uint32_t smem_u32(const void* p) {
    uint32_t a;
    asm("{ .reg .u64 t; cvta.to.shared.u64 t, %1; cvt.u32.u64 %0, t; }" : "=r"(a) : "l"(p));
    return a;
}
__device__ __forceinline__ void cp16(uint32_t saddr, const void* gptr) {
    asm volatile("cp.async.cg.shared.global [%0], [%1], 16;"
                 :: "r"(saddr), "l"(gptr) : "memory");
}
__device__ __forceinline__ void ldsm4(uint32_t* r, uint32_t addr) {
    asm volatile("ldmatrix.sync.aligned.m8n8.x4.shared.b16 {%0,%1,%2,%3}, [%4];"
                 : "=r"(r[0]), "=r"(r[1]), "=r"(r[2]), "=r"(r[3]) : "r"(addr));
}
__device__ __forceinline__ void mma16816(float* c, const uint32_t* a,
                                         uint32_t b0, uint32_t b1) {
    asm volatile(
        "mma.sync.aligned.m16n8k16.row.col.f32.f16.f16.f32 "
        "{%0,%1,%2,%3}, {%4,%5,%6,%7}, {%8,%9}, {%0,%1,%2,%3};"
        : "+f"(c[0]), "+f"(c[1]), "+f"(c[2]), "+f"(c[3])
        : "r"(a[0]), "r"(a[1]), "r"(a[2]), "r"(a[3]), "r"(b0), "r"(b1));
}

// ================= fused init =================
__global__ void init_k(const void* __restrict__ etype,
                       const float* __restrict__ bases,
                       const float* __restrict__ coeff,
                       const float* __restrict__ wself, int E) {
    int i = blockIdx.x * blockDim.x + threadIdx.x;
    if (i < NREL) { g_counts[i] = 0; g_cursor[i] = 0; }
    if (i < SORT_CAP) g_sorted[i] = -1;
    if (i < 32768 && i < E / 2) {
        if (((const int*)etype)[2 * i + 1] != 0 && g_i32 == 0) atomicExch(&g_i32, 1);
    }
    if (i < NREL * D * D) {
        int r = i >> 14, o = (i >> 7) & 127, ii = i & 127;
        float acc = 0.f;
#pragma unroll
        for (int b = 0; b < NBASES; b++)
            acc += __ldg(&coeff[r * NBASES + b]) * __ldg(&bases[b * D * D + ii * D + o]);
        g_W[i] = __float2half_rn(acc);
    }
    if (i < D * D) g_Ws[i] = __float2half_rn(wself[i]);   // already [o][i]
}

// ================= x fp32 -> fp16 pre-convert =================
__global__ void cvt_x_k(const float* __restrict__ x, int nElem4) {
    int i = blockIdx.x * blockDim.x + threadIdx.x;
    if (i < nElem4) {
        float4 v = ((const float4*)x)[i];
        __half2 p0 = __floats2half2_rn(v.x, v.y);
        __half2 p1 = __floats2half2_rn(v.z, v.w);
        ((__half2*)g_xh)[i * 2]     = p0;
        ((__half2*)g_xh)[i * 2 + 1] = p1;
    }
}

// ================= histogram (smem-aggregated) =================
__global__ void hist_k(const void* __restrict__ etype, int E) {
    __shared__ int h[NREL];
    int tid = threadIdx.x;
    if (tid < NREL) h[tid] = 0;
    __syncthreads();
    int i = blockIdx.x * blockDim.x + tid;
    int is32 = g_i32;
    if (i < E) {
        int t = ld_idx(etype, i, is32);
        if (t >= 0 && t < NREL) atomicAdd(&h[t], 1);
    }
    __syncthreads();
    if (tid < NREL && h[tid] > 0) atomicAdd(&g_counts[tid], h[tid]);
}

// ================= scatter (scan fused per block) =================
__global__ void scatter_k(const void* __restrict__ etype, int E) {
    __shared__ int cnt[NREL], base[NREL], soff[NREL];
    int tid = threadIdx.x;
    if (tid < NREL) cnt[tid] = 0;
    if (tid == 0) {
        int off = 0;
        for (int r = 0; r < NREL; r++) {
            soff[r] = off;
            off += ((g_counts[r] + TILE - 1) / TILE) * TILE;
        }
    }
    __syncthreads();
    int i = blockIdx.x * blockDim.x + tid;
    int is32 = g_i32;
    int t = -1, rank = 0;
    if (i < E) {
        t = ld_idx(etype, i, is32);
        if (t >= 0 && t < NREL) rank = atomicAdd(&cnt[t], 1);
        else t = -1;
    }
    __syncthreads();
    if (tid < NREL && cnt[tid] > 0) base[tid] = atomicAdd(&g_cursor[tid], cnt[tid]);
    __syncthreads();
    if (t >= 0) g_sorted[soff[t] + base[t] + rank] = i;
}

// ================= GEMM =================
extern __shared__ char smem_raw[];

// load W tile from global [o][i] fp16 (2048 16B chunks), 256 threads
__device__ __forceinline__ void load_w(char* sm, const __half* W, int tid) {
#pragma unroll
    for (int it = 0; it < 8; it++) {
        int c = it * 256 + tid;
        int o = c >> 4, k16 = (c & 15) * 16;
        *(uint4*)(sm + W_OFF + o * ROWB + k16) = ((const uint4*)W)[c];
    }
}

// load indices for tile tIdx, issue cp.async X gather into buffer `buf`; returns rel
__device__ __forceinline__ int prefetch_tile(
    uint32_t xsm, int buf, int tIdx, int nEdgeTiles, int N, int E,
    const void* eidx, const void* etype, int is32, int warp, int lane, int* srowbuf) {
    const bool isEdge = tIdx < nEdgeTiles;
    const int loc = isEdge ? tIdx * TILE : (tIdx - nEdgeTiles) * TILE;
    int rel;
    if (isEdge) {
        int id0 = g_sorted[loc];
        rel = (id0 >= 0) ? ld_idx(etype, id0, is32) : -1;
    } else rel = NREL;

    int r = -1, c = 0;
    if (lane < 8) {
        int e = warp * 8 + lane;
        if (isEdge) {
            int id = g_sorted[loc + e];
            if (id >= 0) {
                r = ld_idx(eidx, id, is32);
                c = ld_idx(eidx, (size_t)E + id, is32);
                if ((unsigned)r >= (unsigned)N) r = -1;
                if ((unsigned)c >= (unsigned)N) c = 0;
            }
        } else {
            int n = loc + e;
            r = (n < N) ? n : -1;
            c = (n < N) ? n : 0;
        }
        srowbuf[e] = r;
    }
    // 8 rows x 16 chunks(16B) over 32 lanes -> 4 cp.async per thread
    const uint32_t xo = xsm + (uint32_t)buf * XTILE_B + (uint32_t)(lane & 15) * 16;
#pragma unroll
    for (int j = 0; j < 4; j++) {
        int e_in = j * 2 + (lane >> 4);
        int cj = __shfl_sync(0xffffffffu, c, e_in);
        const char* g = (const char*)(g_xh + (size_t)cj * D) + (lane & 15) * 16;
        cp16(xo + (uint32_t)(warp * 8 + e_in) * ROWB, g);
    }
    asm volatile("cp.async.commit_group;" ::: "memory");
    return rel;
}

__global__ __launch_bounds__(256, 3)
void gemm_k(const void* __restrict__ eidx,
            const void* __restrict__ etype,
            float* __restrict__ out, int E, int N, int nEdgeTiles, int nTotal) {
    __shared__ int srow2[2][TILE];
    char* sm = smem_raw;
    const int tid = threadIdx.x;
    const int warp = tid >> 5, lane = tid & 31;
    const int is32 = g_i32;

    const int wm = warp & 1, wn = warp >> 1;           // 2x4 warp grid, 32x32 each
    const int gq = lane >> 2, t4 = lane & 3;
    const int ar = (lane & 7) + ((lane >> 3) & 1) * 8;
    const int ac = (lane >> 4) * 8;
    const int bn = (lane >> 4) * 8 + (lane & 7);
    const int bk = ((lane >> 3) & 1) * 8;
    const uint32_t xsm = smem_u32(sm);
    const uint32_t xb0 = xsm + (uint32_t)((wm * 32 + ar) * ROWB + ac * 2);
    const uint32_t wb  = xsm + W_OFF + (uint32_t)((wn * 32 + bn) * ROWB + bk * 2);

    const int t0 = (int)blockIdx.x * CHUNK;
    const int tEnd = min(t0 + CHUNK, nTotal);
    if (t0 >= tEnd) return;

    int cur_w = -2;
    int rel_cur = prefetch_tile(xsm, 0, t0, nEdgeTiles, N, E, eidx, etype,
                                is32, warp, lane, srow2[0]);

    for (int ti = t0; ti < tEnd; ti++) {
        const int buf = (ti - t0) & 1;
        const bool havenext = (ti + 1 < tEnd);
        int rel_next = -1;
        if (havenext)
            rel_next = prefetch_tile(xsm, buf ^ 1, ti + 1, nEdgeTiles, N, E,
                                     eidx, etype, is32, warp, lane, srow2[buf ^ 1]);
        if (rel_cur >= 0 && rel_cur != cur_w) {   // W free: prev mma done + trailing sync
            load_w(sm, (rel_cur < NREL) ? (g_W + (size_t)rel_cur * D * D) : g_Ws, tid);
            cur_w = rel_cur;
        }
        if (havenext) asm volatile("cp.async.wait_group 1;" ::: "memory");
        else          asm volatile("cp.async.wait_group 0;" ::: "memory");
        __syncthreads();                          // X[buf]/W/srow visible

        if (rel_cur >= 0) {
            const uint32_t xb = xb0 + (uint32_t)buf * XTILE_B;
            float acc[2][4][4];
#pragma unroll
            for (int mt = 0; mt < 2; mt++)
#pragma unroll
                for (int nt = 0; nt < 4; nt++)
#pragma unroll
                    for (int q = 0; q < 4; q++) acc[mt][nt][q] = 0.f;

#pragma unroll
            for (int kk = 0; kk < 8; kk++) {
                const uint32_t koff = (uint32_t)(kk * 16 * 2);
                uint32_t a[2][4], b[2][4];
#pragma unroll
                for (int mt = 0; mt < 2; mt++)
                    ldsm4(a[mt], xb + (uint32_t)(mt * 16 * ROWB) + koff);
#pragma unroll
                for (int n2 = 0; n2 < 2; n2++)
                    ldsm4(b[n2], wb + (uint32_t)(n2 * 16 * ROWB) + koff);
#pragma unroll
                for (int mt = 0; mt < 2; mt++)
#pragma unroll
                    for (int nt = 0; nt < 4; nt++)
                        mma16816(acc[mt][nt], a[mt], b[nt >> 1][(nt & 1) * 2],
                                 b[nt >> 1][(nt & 1) * 2 + 1]);
            }

#pragma unroll
            for (int mt = 0; mt < 2; mt++) {
                const int m0 = wm * 32 + mt * 16 + gq;
                const int r0 = srow2[buf][m0], r1 = srow2[buf][m0 + 8];
#pragma unroll
                for (int nt = 0; nt < 4; nt++) {
                    const int col = wn * 32 + nt * 8 + 2 * t4;
                    if (r0 >= 0) red2(out + (size_t)r0 * D + col, acc[mt][nt][0], acc[mt][nt][1]);
                    if (r1 >= 0) red2(out + (size_t)r1 * D + col, acc[mt][nt][2], acc[mt][nt][3]);
                }
            }
        }
        __syncthreads();                          // protect X[buf]/W for next prefetch
        rel_cur = rel_next;
    }
}

// ================= host launcher =================
extern "C" void kernel_launch(void* const* d_in, const int* in_sizes, int n_in,
                              void* d_out, int out_size) {
    const float* x     = (const float*)d_in[0];
    const void*  eidx  = d_in[1];
    const void*  etype = d_in[2];
    const float* bases = (const float*)d_in[3];
    const float* coeff = (const float*)d_in[4];
    const float* wself = (const float*)d_in[5];
    float* out = (float*)d_out;

    const int N = in_sizes[0] / D;
    const int E = in_sizes[2];
    const int nSelfTiles = (N + TILE - 1) / TILE;
    const int nTotal = NTILES + nSelfTiles;
    const int nBlocks = (nTotal + CHUNK - 1) / CHUNK;
    const int nElem4 = N * D / 4;

    cudaFuncSetAttribute(gemm_k, cudaFuncAttributeMaxDynamicSharedMemorySize, GEMM_SMEM);
    cudaFuncSetAttribute(gemm_k, cudaFuncAttributePreferredSharedMemoryCarveout, 100);

    cudaMemsetAsync(out, 0, (size_t)out_size * sizeof(float));
    init_k<<<(SORT_CAP + 255) / 256, 256>>>(etype, bases, coeff, wself, E);
    cvt_x_k<<<(nElem4 + 255) / 256, 256>>>(x, nElem4);
    hist_k<<<(E + 255) / 256, 256>>>(etype, E);
    scatter_k<<<(E + 255) / 256, 256>>>(etype, E);
    gemm_k<<<nBlocks, 256, GEMM_SMEM>>>(eidx, etype, out, E, N, NTILES, nTotal);
}

// round 14
// speedup vs baseline: 1.0355x; 1.0289x over previous
#include <cuda_runtime.h>
#include <cuda_fp16.h>
#include <cstdint>
#include <cstring>

#define D        128
#define NREL     16
#define NBASES   8
#define TILE     64                                // rows per tile
#define CHUNK    4                                 // tiles per CTA
#define MAXE     600000
#define NMAX     100352
#define NTILES   ((MAXE / TILE) + NREL + 2)        // 9393 edge-tile capacity
#define SORT_CAP (NTILES * TILE)                   // 601152

// ---- smem layout (fp16 tiles, row stride 136 elems = 272B) ----
#define LDA      136
#define ROWB     (LDA * 2)          // 272 bytes per row
#define XTILE_B  (TILE * ROWB)      // 17408 per X buffer
#define WTILE_B  (D * ROWB)         // 34816 (128-row W tile)
#define W_OFF    (2 * XTILE_B)      // edge kernel: 2 X buffers then W
#define GEMM_SMEM (2 * XTILE_B + WTILE_B)          // 69632 -> 3 CTAs/SM
#define SELF_SMEM (XTILE_B + WTILE_B)              // 52224 -> 4 CTAs/SM

// -------- device scratch --------
__device__ __align__(16) __half g_xh[(size_t)NMAX * D];  // pre-converted X
__device__ __align__(16) __half g_W[NREL * D * D];   // [r][o][i] fp16
__device__ __align__(16) __half g_Ws[D * D];         // w_self [o][i] fp16
__device__ int g_counts[NREL];
__device__ int g_cursor[NREL];
__device__ int g_sorted[SORT_CAP];
__device__ int g_i32 = 0;   // sticky dtype flag: deterministic for fixed inputs

__device__ __forceinline__ int ld_idx(const void* p, size_t i, int is32) {
    return is32 ? ((const int*)p)[i] : (int)((const long long*)p)[i];
}
__device__ __forceinline__ void red2(float* p, float a, float b) {
    asm volatile("red.global.add.v2.f32 [%0], {%1,%2};"
                 :: "l"(p), "f"(a), "f"(b) : "memory");
}
__device__ __forceinline__ uint32_t smem_u32(const void* p) {
    uint32_t a;
    asm("{ .reg .u64 t; cvta.to.shared.u64 t, %1; cvt.u32.u64 %0, t; }" : "=r"(a) : "l"(p));
    return a;
}
__device__ __forceinline__ void cp16(uint32_t saddr, const void* gptr) {
    asm volatile("cp.async.cg.shared.global [%0], [%1], 16;"
                 :: "r"(saddr), "l"(gptr) : "memory");
}
__device__ __forceinline__ void ldsm4(uint32_t* r, uint32_t addr) {
    asm volatile("ldmatrix.sync.aligned.m8n8.x4.shared.b16 {%0,%1,%2,%3}, [%4];"
                 : "=r"(r[0]), "=r"(r[1]), "=r"(r[2]), "=r"(r[3]) : "r"(addr));
}
__device__ __forceinline__ void mma16816(float* c, const uint32_t* a,
                                         uint32_t b0, uint32_t b1) {
    asm volatile(
        "mma.sync.aligned.m16n8k16.row.col.f32.f16.f16.f32 "
        "{%0,%1,%2,%3}, {%4,%5,%6,%7}, {%8,%9}, {%0,%1,%2,%3};"
        : "+f"(c[0]), "+f"(c[1]), "+f"(c[2]), "+f"(c[3])
        : "r"(a[0]), "r"(a[1]), "r"(a[2]), "r"(a[3]), "r"(b0), "r"(b1));
}

// ================= fused init + x convert =================
__global__ void initcvt_k(const void* __restrict__ etype,
                          const float* __restrict__ bases,
                          const float* __restrict__ coeff,
                          const float* __restrict__ wself,
                          const float* __restrict__ x, int E, int nElem4) {
    int i = blockIdx.x * blockDim.x + threadIdx.x;
    if (i < NREL) { g_counts[i] = 0; g_cursor[i] = 0; }
    if (i < SORT_CAP) g_sorted[i] = -1;
    if (i < 32768 && i < E / 2) {
        if (((const int*)etype)[2 * i + 1] != 0 && g_i32 == 0) atomicExch(&g_i32, 1);
    }
    if (i < NREL * D * D) {
        int r = i >> 14, o = (i >> 7) & 127, ii = i & 127;
        float acc = 0.f;
#pragma unroll
        for (int b = 0; b < NBASES; b++)
            acc += __ldg(&coeff[r * NBASES + b]) * __ldg(&bases[b * D * D + ii * D + o]);
        g_W[i] = __float2half_rn(acc);
    }
    if (i < D * D) g_Ws[i] = __float2half_rn(wself[i]);   // already [o][i]
    if (i < nElem4) {
        float4 v = ((const float4*)x)[i];
        ((__half2*)g_xh)[i * 2]     = __floats2half2_rn(v.x, v.y);
        ((__half2*)g_xh)[i * 2 + 1] = __floats2half2_rn(v.z, v.w);
    }
}

// ================= histogram (smem-aggregated) =================
__global__ void hist_k(const void* __restrict__ etype, int E) {
    __shared__ int h[NREL];
    int tid = threadIdx.x;
    if (tid < NREL) h[tid] = 0;
    __syncthreads();
    int i = blockIdx.x * blockDim.x + tid;
    int is32 = g_i32;
    if (i < E) {
        int t = ld_idx(etype, i, is32);
        if (t >= 0 && t < NREL) atomicAdd(&h[t], 1);
    }
    __syncthreads();
    if (tid < NREL && h[tid] > 0) atomicAdd(&g_counts[tid], h[tid]);
}

// ================= scatter (scan fused per block) =================
__global__ void scatter_k(const void* __restrict__ etype, int E) {
    __shared__ int cnt[NREL], base[NREL], soff[NREL];
    int tid = threadIdx.x;
    if (tid < NREL) cnt[tid] = 0;
    if (tid == 0) {
        int off = 0;
        for (int r = 0; r < NREL; r++) {
            soff[r] = off;
            off += ((g_counts[r] + TILE - 1) / TILE) * TILE;
        }
    }
    __syncthreads();
    int i = blockIdx.x * blockDim.x + tid;
    int is32 = g_i32;
    int t = -1, rank = 0;
    if (i < E) {
        t = ld_idx(etype, i, is32);
        if (t >= 0 && t < NREL) rank = atomicAdd(&cnt[t], 1);
        else t = -1;
    }
    __syncthreads();
    if (tid < NREL && cnt[tid] > 0) base[tid] = atomicAdd(&g_cursor[tid], cnt[tid]);
    __syncthreads();
    if (t >= 0) g_sorted[soff[t] + base[t] + rank] = i;
}

// ================= GEMM =================
extern __shared__ char smem_raw[];

// load W tile into smem at woff from global [o][i] fp16 (2048 16B chunks), 256 threads
__device__ __forceinline__ void load_w(char* sm, uint32_t woff, const __half* W, int tid) {
#pragma unroll
    for (int it = 0; it < 8; it++) {
        int c = it * 256 + tid;
        int o = c >> 4, k16 = (c & 15) * 16;
        *(uint4*)(sm + woff + o * ROWB + k16) = ((const uint4*)W)[c];
    }
}

// load indices for edge tile tIdx, issue cp.async X gather into buffer `buf`; returns rel
__device__ __forceinline__ int prefetch_tile(
    uint32_t xsm, int buf, int tIdx, int N, int E,
    const void* eidx, const void* etype, int is32, int warp, int lane, int* srowbuf) {
    const int loc = tIdx * TILE;
    int id0 = g_sorted[loc];
    int rel = (id0 >= 0) ? ld_idx(etype, id0, is32) : -1;

    int r = -1, c = 0;
    if (lane < 8) {
        int e = warp * 8 + lane;
        int id = g_sorted[loc + e];
        if (id >= 0) {
            r = ld_idx(eidx, id, is32);
            c = ld_idx(eidx, (size_t)E + id, is32);
            if ((unsigned)r >= (unsigned)N) r = -1;
            if ((unsigned)c >= (unsigned)N) c = 0;
        }
        srowbuf[e] = r;
    }
    const uint32_t xo = xsm + (uint32_t)buf * XTILE_B + (uint32_t)(lane & 15) * 16;
#pragma unroll
    for (int j = 0; j < 4; j++) {
        int e_in = j * 2 + (lane >> 4);
        int cj = __shfl_sync(0xffffffffu, c, e_in);
        const char* g = (const char*)(g_xh + (size_t)cj * D) + (lane & 15) * 16;
        cp16(xo + (uint32_t)(warp * 8 + e_in) * ROWB, g);
    }
    asm volatile("cp.async.commit_group;" ::: "memory");
    return rel;
}

// ---- edge GEMM: cp.async double-buffered, red2 epilogue ----
__global__ __launch_bounds__(256, 3)
void gemm_k(const void* __restrict__ eidx,
            const void* __restrict__ etype,
            float* __restrict__ out, int E, int N, int nEdgeTiles) {
    __shared__ int srow2[2][TILE];
    char* sm = smem_raw;
    const int tid = threadIdx.x;
    const int warp = tid >> 5, lane = tid & 31;
    const int is32 = g_i32;

    const int wm = warp & 1, wn = warp >> 1;           // 2x4 warp grid, 32x32 each
    const int gq = lane >> 2, t4 = lane & 3;
    const int ar = (lane & 7) + ((lane >> 3) & 1) * 8;
    const int ac = (lane >> 4) * 8;
    const int bn = (lane >> 4) * 8 + (lane & 7);
    const int bk = ((lane >> 3) & 1) * 8;
    const uint32_t xsm = smem_u32(sm);
    const uint32_t xb0 = xsm + (uint32_t)((wm * 32 + ar) * ROWB + ac * 2);
    const uint32_t wb  = xsm + W_OFF + (uint32_t)((wn * 32 + bn) * ROWB + bk * 2);

    const int t0 = (int)blockIdx.x * CHUNK;
    const int tEnd = min(t0 + CHUNK, nEdgeTiles);
    if (t0 >= tEnd) return;

    int cur_w = -2;
    int rel_cur = prefetch_tile(xsm, 0, t0, N, E, eidx, etype, is32, warp, lane, srow2[0]);

    for (int ti = t0; ti < tEnd; ti++) {
        const int buf = (ti - t0) & 1;
        const bool havenext = (ti + 1 < tEnd);
        int rel_next = -1;
        if (havenext)
            rel_next = prefetch_tile(xsm, buf ^ 1, ti + 1, N, E, eidx, etype,
                                     is32, warp, lane, srow2[buf ^ 1]);
        if (rel_cur >= 0 && rel_cur != cur_w) {
            load_w(sm, W_OFF, g_W + (size_t)rel_cur * D * D, tid);
            cur_w = rel_cur;
        }
        if (havenext) asm volatile("cp.async.wait_group 1;" ::: "memory");
        else          asm volatile("cp.async.wait_group 0;" ::: "memory");
        __syncthreads();

        if (rel_cur >= 0) {
            const uint32_t xb = xb0 + (uint32_t)buf * XTILE_B;
            float acc[2][4][4];
#pragma unroll
            for (int mt = 0; mt < 2; mt++)
#pragma unroll
                for (int nt = 0; nt < 4; nt++)
#pragma unroll
                    for (int q = 0; q < 4; q++) acc[mt][nt][q] = 0.f;

#pragma unroll
            for (int kk = 0; kk < 8; kk++) {
                const uint32_t koff = (uint32_t)(kk * 16 * 2);
                uint32_t a[2][4], b[2][4];
#pragma unroll
                for (int mt = 0; mt < 2; mt++)
                    ldsm4(a[mt], xb + (uint32_t)(mt * 16 * ROWB) + koff);
#pragma unroll
                for (int n2 = 0; n2 < 2; n2++)
                    ldsm4(b[n2], wb + (uint32_t)(n2 * 16 * ROWB) + koff);
#pragma unroll
                for (int mt = 0; mt < 2; mt++)
#pragma unroll
                    for (int nt = 0; nt < 4; nt++)
                        mma16816(acc[mt][nt], a[mt], b[nt >> 1][(nt & 1) * 2],
                                 b[nt >> 1][(nt & 1) * 2 + 1]);
            }

#pragma unroll
            for (int mt = 0; mt < 2; mt++) {
                const int m0 = wm * 32 + mt * 16 + gq;
                const int r0 = srow2[buf][m0], r1 = srow2[buf][m0 + 8];
#pragma unroll
                for (int nt = 0; nt < 4; nt++) {
                    const int col = wn * 32 + nt * 8 + 2 * t4;
                    if (r0 >= 0) red2(out + (size_t)r0 * D + col, acc[mt][nt][0], acc[mt][nt][1]);
                    if (r1 >= 0) red2(out + (size_t)r1 * D + col, acc[mt][nt][2], acc[mt][nt][3]);
                }
            }
        }
        __syncthreads();
        rel_cur = rel_next;
    }
}

// ---- self-loop GEMM: plain-ST epilogue (replaces the output memset) ----
__global__ __launch_bounds__(256, 4)
void selfloop_k(float* __restrict__ out, int N, int nTiles) {
    char* sm = smem_raw;                 // X at 0, W at XTILE_B
    const int tid = threadIdx.x;
    const int warp = tid >> 5, lane = tid & 31;

    const int wm = warp & 1, wn = warp >> 1;
    const int gq = lane >> 2, t4 = lane & 3;
    const int ar = (lane & 7) + ((lane >> 3) & 1) * 8;
    const int ac = (lane >> 4) * 8;
    const int bn = (lane >> 4) * 8 + (lane & 7);
    const int bk = ((lane >> 3) & 1) * 8;
    const uint32_t xsm = smem_u32(sm);
    const uint32_t xb = xsm + (uint32_t)((wm * 32 + ar) * ROWB + ac * 2);
    const uint32_t wb = xsm + XTILE_B + (uint32_t)((wn * 32 + bn) * ROWB + bk * 2);

    load_w(sm, XTILE_B, g_Ws, tid);      // once per CTA

    const int t0 = (int)blockIdx.x * CHUNK;
    const int tEnd = min(t0 + CHUNK, nTiles);

    for (int ti = t0; ti < tEnd; ti++) {
        const int n0 = ti * TILE;
        // contiguous X rows n0..n0+63 (g_xh padded to NMAX; OOB rows read zeros)
#pragma unroll
        for (int it = 0; it < 4; it++) {
            int c = it * 256 + tid;              // 1024 16B chunks
            int row = c >> 4, k16 = (c & 15) * 16;
            *(uint4*)(sm + row * ROWB + k16) =
                *(const uint4*)((const char*)(g_xh + (size_t)(n0 + row) * D) + k16);
        }
        __syncthreads();

        float acc[2][4][4];
#pragma unroll
        for (int mt = 0; mt < 2; mt++)
#pragma unroll
            for (int nt = 0; nt < 4; nt++)
#pragma unroll
                for (int q = 0; q < 4; q++) acc[mt][nt][q] = 0.f;

#pragma unroll
        for (int kk = 0; kk < 8; kk++) {
            const uint32_t koff = (uint32_t)(kk * 16 * 2);
            uint32_t a[2][4], b[2][4];
#pragma unroll
            for (int mt = 0; mt < 2; mt++)
                ldsm4(a[mt], xb + (uint32_t)(mt * 16 * ROWB) + koff);
#pragma unroll
            for (int n2 = 0; n2 < 2; n2++)
                ldsm4(b[n2], wb + (uint32_t)(n2 * 16 * ROWB) + koff);
#pragma unroll
            for (int mt = 0; mt < 2; mt++)
#pragma unroll
                for (int nt = 0; nt < 4; nt++)
                    mma16816(acc[mt][nt], a[mt], b[nt >> 1][(nt & 1) * 2],
                             b[nt >> 1][(nt & 1) * 2 + 1]);
        }

        // plain stores: every out element in rows [n0, n0+64) ∩ [0,N) written once
#pragma unroll
        for (int mt = 0; mt < 2; mt++) {
            const int m0 = wm * 32 + mt * 16 + gq;
            const int r0 = n0 + m0, r1 = n0 + m0 + 8;
#pragma unroll
            for (int nt = 0; nt < 4; nt++) {
                const int col = wn * 32 + nt * 8 + 2 * t4;
                if (r0 < N) *(float2*)(out + (size_t)r0 * D + col) =
                    make_float2(acc[mt][nt][0], acc[mt][nt][1]);
                if (r1 < N) *(float2*)(out + (size_t)r1 * D + col) =
                    make_float2(acc[mt][nt][2], acc[mt][nt][3]);
            }
        }
        __syncthreads();
    }
}

// ================= host launcher =================
extern "C" void kernel_launch(void* const* d_in, const int* in_sizes, int n_in,
                              void* d_out, int out_size) {
    const float* x     = (const float*)d_in[0];
    const void*  eidx  = d_in[1];
    const void*  etype = d_in[2];
    const float* bases = (const float*)d_in[3];
    const float* coeff = (const float*)d_in[4];
    const float* wself = (const float*)d_in[5];
    float* out = (float*)d_out;

    const int N = in_sizes[0] / D;
    const int E = in_sizes[2];
    const int nSelfTiles = (N + TILE - 1) / TILE;
    const int nElem4 = N * D / 4;
    const int nEdgeBlocks = (NTILES + CHUNK - 1) / CHUNK;
    const int nSelfBlocks = (nSelfTiles + CHUNK - 1) / CHUNK;

    cudaFuncSetAttribute(gemm_k, cudaFuncAttributeMaxDynamicSharedMemorySize, GEMM_SMEM);
    cudaFuncSetAttribute(gemm_k, cudaFuncAttributePreferredSharedMemoryCarveout, 100);
    cudaFuncSetAttribute(selfloop_k, cudaFuncAttributeMaxDynamicSharedMemorySize, SELF_SMEM);
    cudaFuncSetAttribute(selfloop_k, cudaFuncAttributePreferredSharedMemoryCarveout, 100);

    initcvt_k<<<(nElem4 + 255) / 256, 256>>>(etype, bases, coeff, wself, x, E, nElem4);
    hist_k<<<(E + 255) / 256, 256>>>(etype, E);
    scatter_k<<<(E + 255) / 256, 256>>>(etype, E);
    selfloop_k<<<nSelfBlocks, 256, SELF_SMEM>>>(out, N, nSelfTiles);   // writes ALL of out
    gemm_k<<<nEdgeBlocks, 256, GEMM_SMEM>>>(eidx, etype, out, E, N, NTILES);
}